// round 2
// baseline (speedup 1.0000x reference)
#include <cuda_runtime.h>

// MultiHeadAttention: B=2, N=4096, E=512, H=8, D=64
// Output = concat(flatten(out[B,N,E]), flatten(attn[B,H,N,N]))

#define NH   8
#define HD   64
#define SEQ  4096
#define EMB  512
#define NB   2
#define MTOT (NB * SEQ)   // 8192
#define BHT  (NB * NH)    // 16

// scratch (device globals — allocation inside kernel_launch is forbidden)
__device__ float g_q[(size_t)BHT * SEQ * HD];
__device__ float g_k[(size_t)BHT * SEQ * HD];
__device__ float g_v[(size_t)BHT * SEQ * HD];
__device__ float g_o[(size_t)BHT * SEQ * HD];
__device__ float g_m[BHT * SEQ];
__device__ float g_l[BHT * SEQ];

// ---------------------------------------------------------------------------
// Input projection: out_bhnd = X @ W^T + b, scattered to (B,H,N,D) layout.
// Tile 64x64, BK=16, 128 threads, each thread 8x4.
// ---------------------------------------------------------------------------
__global__ __launch_bounds__(128) void proj_in_kernel(
    const float* __restrict__ X, const float* __restrict__ W,
    const float* __restrict__ bias, int sel)
{
    __shared__ float As[16][65];
    __shared__ float Bs[16][65];
    float* outp = (sel == 0) ? g_q : (sel == 1) ? g_k : g_v;

    const int t  = threadIdx.x;
    const int tx = t & 15, ty = t >> 4;
    const int row0 = blockIdx.x * 64, col0 = blockIdx.y * 64;
    const int lr = t >> 1;          // 0..63
    const int lk = (t & 1) * 8;     // 0 or 8

    float acc[8][4];
#pragma unroll
    for (int i = 0; i < 8; i++)
#pragma unroll
        for (int j = 0; j < 4; j++) acc[i][j] = 0.f;

    const float* Xr = X + (size_t)(row0 + lr) * EMB;
    const float* Wr = W + (size_t)(col0 + lr) * EMB;

    for (int k0 = 0; k0 < EMB; k0 += 16) {
        float4 a0 = *(const float4*)(Xr + k0 + lk);
        float4 a1 = *(const float4*)(Xr + k0 + lk + 4);
        float4 b0 = *(const float4*)(Wr + k0 + lk);
        float4 b1 = *(const float4*)(Wr + k0 + lk + 4);
        __syncthreads();
        As[lk+0][lr]=a0.x; As[lk+1][lr]=a0.y; As[lk+2][lr]=a0.z; As[lk+3][lr]=a0.w;
        As[lk+4][lr]=a1.x; As[lk+5][lr]=a1.y; As[lk+6][lr]=a1.z; As[lk+7][lr]=a1.w;
        Bs[lk+0][lr]=b0.x; Bs[lk+1][lr]=b0.y; Bs[lk+2][lr]=b0.z; Bs[lk+3][lr]=b0.w;
        Bs[lk+4][lr]=b1.x; Bs[lk+5][lr]=b1.y; Bs[lk+6][lr]=b1.z; Bs[lk+7][lr]=b1.w;
        __syncthreads();
#pragma unroll
        for (int kk = 0; kk < 16; kk++) {
            float a[8], b[4];
#pragma unroll
            for (int i = 0; i < 8; i++) a[i] = As[kk][ty*8+i];
#pragma unroll
            for (int j = 0; j < 4; j++) b[j] = Bs[kk][tx*4+j];
#pragma unroll
            for (int i = 0; i < 8; i++)
#pragma unroll
                for (int j = 0; j < 4; j++) acc[i][j] = fmaf(a[i], b[j], acc[i][j]);
        }
    }

    // col block == exactly one head (BN = 64 = HD)
    const int h  = col0 >> 6;
    const int d0 = tx * 4;
    float4 bz = *(const float4*)(bias + col0 + tx*4);
#pragma unroll
    for (int i = 0; i < 8; i++) {
        int m  = row0 + ty*8 + i;
        int bb = m >> 12, n = m & (SEQ - 1);
        float4 v;
        v.x = acc[i][0] + bz.x; v.y = acc[i][1] + bz.y;
        v.z = acc[i][2] + bz.z; v.w = acc[i][3] + bz.w;
        *(float4*)&outp[((size_t)((bb*NH + h)*SEQ + n)) * HD + d0] = v;
    }
}

// ---------------------------------------------------------------------------
// Scores: S = Q K^T / 8 per (b,h); writes raw scores into attn buffer and
// computes per-row running max (m) and sum-exp (l) with online rescale.
// CTA = 64 query rows x full key loop. 128 threads, 8x4 per thread.
// ---------------------------------------------------------------------------
__global__ __launch_bounds__(128) void scores_kernel(float* __restrict__ attn)
{
    __shared__ float Qs[64][65];
    __shared__ float Ks[64][65];
    __shared__ float rowm[64], rowl[64];

    const int t  = threadIdx.x;
    const int tx = t & 15, ty = t >> 4;
    const int bh = blockIdx.y;
    const int q0 = blockIdx.x * 64;

    const float* qb = g_q + (size_t)(bh*SEQ + q0) * HD;
#pragma unroll
    for (int it = 0; it < 8; it++) {
        int f = (t + it*128) * 4;
        float4 v = *(const float4*)(qb + f);
        int r = f >> 6, kk = f & 63;
        Qs[r][kk]=v.x; Qs[r][kk+1]=v.y; Qs[r][kk+2]=v.z; Qs[r][kk+3]=v.w;
    }
    if (t < 64) { rowm[t] = -1e30f; rowl[t] = 0.f; }

    const size_t abase = (size_t)(bh*SEQ + q0) * SEQ;

    for (int kt = 0; kt < SEQ/64; kt++) {
        const float* kb = g_k + (size_t)(bh*SEQ + kt*64) * HD;
        __syncthreads();
#pragma unroll
        for (int it = 0; it < 8; it++) {
            int f = (t + it*128) * 4;
            float4 v = *(const float4*)(kb + f);
            int r = f >> 6, kk = f & 63;
            Ks[r][kk]=v.x; Ks[r][kk+1]=v.y; Ks[r][kk+2]=v.z; Ks[r][kk+3]=v.w;
        }
        __syncthreads();

        float acc[8][4];
#pragma unroll
        for (int i = 0; i < 8; i++)
#pragma unroll
            for (int j = 0; j < 4; j++) acc[i][j] = 0.f;

#pragma unroll 16
        for (int kk = 0; kk < 64; kk++) {
            float a[8], b[4];
#pragma unroll
            for (int i = 0; i < 8; i++) a[i] = Qs[ty*8+i][kk];
#pragma unroll
            for (int j = 0; j < 4; j++) b[j] = Ks[tx*4+j][kk];
#pragma unroll
            for (int i = 0; i < 8; i++)
#pragma unroll
                for (int j = 0; j < 4; j++) acc[i][j] = fmaf(a[i], b[j], acc[i][j]);
        }

#pragma unroll
        for (int i = 0; i < 8; i++) {
            const int r = ty*8 + i;
            float s0 = acc[i][0]*0.125f, s1 = acc[i][1]*0.125f;
            float s2 = acc[i][2]*0.125f, s3 = acc[i][3]*0.125f;
            *(float4*)&attn[abase + (size_t)r*SEQ + kt*64 + tx*4] =
                make_float4(s0, s1, s2, s3);
            float tm = fmaxf(fmaxf(s0,s1), fmaxf(s2,s3));
#pragma unroll
            for (int mk = 8; mk; mk >>= 1)
                tm = fmaxf(tm, __shfl_xor_sync(0xffffffffu, tm, mk, 16));
            float mnew = fmaxf(rowm[r], tm);
            float se = __expf(s0-mnew)+__expf(s1-mnew)+__expf(s2-mnew)+__expf(s3-mnew);
#pragma unroll
            for (int mk = 8; mk; mk >>= 1)
                se += __shfl_xor_sync(0xffffffffu, se, mk, 16);
            if (tx == 0) {   // each half-warp exclusively owns its 8 rows
                rowl[r] = rowl[r]*__expf(rowm[r]-mnew) + se;
                rowm[r] = mnew;
            }
        }
    }
    __syncthreads();
    if (t < 64) {
        g_m[bh*SEQ + q0 + t] = rowm[t];
        g_l[bh*SEQ + q0 + t] = rowl[t];
    }
}

// ---------------------------------------------------------------------------
// Normalize + PV: reads raw scores, writes normalized probs back to attn
// (the required output), accumulates O = P @ V into g_o (B,H,N,D).
// ---------------------------------------------------------------------------
__global__ __launch_bounds__(128) void av_kernel(float* __restrict__ attn)
{
    __shared__ float Ps[64][65];
    __shared__ float Vs[64][65];
    __shared__ float rm[64], rli[64];

    const int t  = threadIdx.x;
    const int tx = t & 15, ty = t >> 4;
    const int bh = blockIdx.y;
    const int q0 = blockIdx.x * 64;

    if (t < 64) {
        rm[t]  = g_m[bh*SEQ + q0 + t];
        rli[t] = 1.0f / g_l[bh*SEQ + q0 + t];
    }
    __syncthreads();

    float acc[8][4];
#pragma unroll
    for (int i = 0; i < 8; i++)
#pragma unroll
        for (int j = 0; j < 4; j++) acc[i][j] = 0.f;

    const size_t abase = (size_t)(bh*SEQ + q0) * SEQ;

    for (int kt = 0; kt < SEQ/64; kt++) {
        __syncthreads();
#pragma unroll
        for (int it = 0; it < 8; it++) {
            int f = (t + it*128) * 4;
            int r = f >> 6, kk = f & 63;
            size_t gi = abase + (size_t)r*SEQ + kt*64 + kk;
            float4 s = *(const float4*)&attn[gi];
            float mm = rm[r], li = rli[r];
            float4 p;
            p.x = __expf(s.x-mm)*li; p.y = __expf(s.y-mm)*li;
            p.z = __expf(s.z-mm)*li; p.w = __expf(s.w-mm)*li;
            *(float4*)&attn[gi] = p;                 // final attn output
            Ps[r][kk]=p.x; Ps[r][kk+1]=p.y; Ps[r][kk+2]=p.z; Ps[r][kk+3]=p.w;
        }
        const float* vb = g_v + (size_t)(bh*SEQ + kt*64) * HD;
#pragma unroll
        for (int it = 0; it < 8; it++) {
            int f = (t + it*128) * 4;
            float4 v = *(const float4*)(vb + f);
            int r = f >> 6, kk = f & 63;
            Vs[r][kk]=v.x; Vs[r][kk+1]=v.y; Vs[r][kk+2]=v.z; Vs[r][kk+3]=v.w;
        }
        __syncthreads();

#pragma unroll 16
        for (int kk = 0; kk < 64; kk++) {
            float a[8], b[4];
#pragma unroll
            for (int i = 0; i < 8; i++) a[i] = Ps[ty*8+i][kk];
#pragma unroll
            for (int j = 0; j < 4; j++) b[j] = Vs[kk][tx*4+j];
#pragma unroll
            for (int i = 0; i < 8; i++)
#pragma unroll
                for (int j = 0; j < 4; j++) acc[i][j] = fmaf(a[i], b[j], acc[i][j]);
        }
    }

    float* ob = g_o + (size_t)(bh*SEQ + q0) * HD;
#pragma unroll
    for (int i = 0; i < 8; i++) {
        int r = ty*8 + i;
        *(float4*)&ob[(size_t)r*HD + tx*4] =
            make_float4(acc[i][0], acc[i][1], acc[i][2], acc[i][3]);
    }
}

// ---------------------------------------------------------------------------
// Output projection: out[m][c] = sum_c' Xeff[m][c'] * Wo[c][c'] + bo[c]
// where Xeff gathers from g_o in (B,H,N,D) layout.
// ---------------------------------------------------------------------------
__global__ __launch_bounds__(128) void proj_out_kernel(
    const float* __restrict__ W, const float* __restrict__ bias,
    float* __restrict__ out)
{
    __shared__ float As[16][65];
    __shared__ float Bs[16][65];

    const int t  = threadIdx.x;
    const int tx = t & 15, ty = t >> 4;
    const int row0 = blockIdx.x * 64, col0 = blockIdx.y * 64;
    const int lr = t >> 1;
    const int lk = (t & 1) * 8;

    const int m  = row0 + lr;
    const int bb = m >> 12, n = m & (SEQ - 1);

    float acc[8][4];
#pragma unroll
    for (int i = 0; i < 8; i++)
#pragma unroll
        for (int j = 0; j < 4; j++) acc[i][j] = 0.f;

    const float* Wr = W + (size_t)(col0 + lr) * EMB;

    for (int k0 = 0; k0 < EMB; k0 += 16) {
        int c0 = k0 + lk;                 // 8-elem chunk stays within one head
        int h = c0 >> 6, d = c0 & 63;
        const float* xr = g_o + ((size_t)((bb*NH + h)*SEQ + n)) * HD + d;
        float4 a0 = *(const float4*)(xr);
        float4 a1 = *(const float4*)(xr + 4);
        float4 b0 = *(const float4*)(Wr + k0 + lk);
        float4 b1 = *(const float4*)(Wr + k0 + lk + 4);
        __syncthreads();
        As[lk+0][lr]=a0.x; As[lk+1][lr]=a0.y; As[lk+2][lr]=a0.z; As[lk+3][lr]=a0.w;
        As[lk+4][lr]=a1.x; As[lk+5][lr]=a1.y; As[lk+6][lr]=a1.z; As[lk+7][lr]=a1.w;
        Bs[lk+0][lr]=b0.x; Bs[lk+1][lr]=b0.y; Bs[lk+2][lr]=b0.z; Bs[lk+3][lr]=b0.w;
        Bs[lk+4][lr]=b1.x; Bs[lk+5][lr]=b1.y; Bs[lk+6][lr]=b1.z; Bs[lk+7][lr]=b1.w;
        __syncthreads();
#pragma unroll
        for (int kk = 0; kk < 16; kk++) {
            float a[8], b[4];
#pragma unroll
            for (int i = 0; i < 8; i++) a[i] = As[kk][ty*8+i];
#pragma unroll
            for (int j = 0; j < 4; j++) b[j] = Bs[kk][tx*4+j];
#pragma unroll
            for (int i = 0; i < 8; i++)
#pragma unroll
                for (int j = 0; j < 4; j++) acc[i][j] = fmaf(a[i], b[j], acc[i][j]);
        }
    }

    float4 bz = *(const float4*)(bias + col0 + tx*4);
#pragma unroll
    for (int i = 0; i < 8; i++) {
        int m2 = row0 + ty*8 + i;
        float4 v;
        v.x = acc[i][0] + bz.x; v.y = acc[i][1] + bz.y;
        v.z = acc[i][2] + bz.z; v.w = acc[i][3] + bz.w;
        *(float4*)&out[(size_t)m2*EMB + col0 + tx*4] = v;
    }
}

// ---------------------------------------------------------------------------
extern "C" void kernel_launch(void* const* d_in, const int* in_sizes, int n_in,
                              void* d_out, int out_size)
{
    (void)in_sizes; (void)n_in; (void)out_size;
    const float* query = (const float*)d_in[0];
    const float* key_t = (const float*)d_in[1];
    const float* value = (const float*)d_in[2];
    const float* Wq = (const float*)d_in[3];
    const float* bq = (const float*)d_in[4];
    const float* Wk = (const float*)d_in[5];
    const float* bk = (const float*)d_in[6];
    const float* Wv = (const float*)d_in[7];
    const float* bv = (const float*)d_in[8];
    const float* Wo = (const float*)d_in[9];
    const float* bo = (const float*)d_in[10];

    float* out  = (float*)d_out;
    float* attn = out + (size_t)MTOT * EMB;   // attn region of the tuple output

    dim3 blk(128);
    dim3 gp(MTOT/64, EMB/64);
    proj_in_kernel<<<gp, blk>>>(query, Wq, bq, 0);
    proj_in_kernel<<<gp, blk>>>(key_t, Wk, bk, 1);
    proj_in_kernel<<<gp, blk>>>(value, Wv, bv, 2);

    dim3 ga(SEQ/64, BHT);
    scores_kernel<<<ga, blk>>>(attn);
    av_kernel<<<ga, blk>>>(attn);

    proj_out_kernel<<<gp, blk>>>(Wo, bo, out);
}

// round 5
// speedup vs baseline: 1.1174x; 1.1174x over previous
#include <cuda_runtime.h>
#include <cuda_bf16.h>
#include <cstdint>

// MultiHeadAttention: B=2, N=4096, E=512, H=8, D=64
// Output = concat(flatten(out[B,N,E]), flatten(attn[B,H,N,N]))

#define NH   8
#define HD   64
#define SEQ  4096
#define EMB  512
#define NB   2
#define MTOT (NB * SEQ)   // 8192
#define BHT  (NB * NH)    // 16

// scratch (device globals — allocation inside kernel_launch is forbidden)
__device__ __nv_bfloat16 g_qh[(size_t)BHT * SEQ * HD];
__device__ __nv_bfloat16 g_ql[(size_t)BHT * SEQ * HD];
__device__ __nv_bfloat16 g_kh[(size_t)BHT * SEQ * HD];
__device__ __nv_bfloat16 g_kl[(size_t)BHT * SEQ * HD];
__device__ __nv_bfloat16 g_vth[(size_t)BHT * HD * SEQ];  // V^T: (bh, d, n)
__device__ __nv_bfloat16 g_vtl[(size_t)BHT * HD * SEQ];
__device__ float g_o[(size_t)BHT * SEQ * HD];
__device__ float g_m[BHT * SEQ];
__device__ float g_l[BHT * SEQ];

// ===========================================================================
// helpers
// ===========================================================================
__device__ __forceinline__ uint32_t pack2bf16(float lo, float hi) {
    return ((uint32_t)__bfloat16_as_ushort(__float2bfloat16(hi)) << 16) |
           (uint32_t)__bfloat16_as_ushort(__float2bfloat16(lo));
}
__device__ __forceinline__ void split_hl(float x, float& h, float& l) {
    __nv_bfloat16 b = __float2bfloat16(x);
    h = __bfloat162float(b);
    l = x - h;
}
// pack two floats into hi-bf16x2 and lo-bf16x2 fragments
__device__ __forceinline__ void pack_hl2(float a, float b, uint32_t& hw, uint32_t& lw) {
    float ah, al, bh, bl;
    split_hl(a, ah, al);
    split_hl(b, bh, bl);
    hw = pack2bf16(ah, bh);
    lw = pack2bf16(al, bl);
}

// m16n8k16 bf16 mma, f32 accumulate (baseline PTX, works on target sm_103)
__device__ __forceinline__ void mma16816(float* c, const uint32_t* a, const uint32_t* b) {
    asm volatile(
        "mma.sync.aligned.m16n8k16.row.col.f32.bf16.bf16.f32 "
        "{%0,%1,%2,%3}, {%4,%5,%6,%7}, {%8,%9}, {%0,%1,%2,%3};"
        : "+f"(c[0]), "+f"(c[1]), "+f"(c[2]), "+f"(c[3])
        : "r"(a[0]), "r"(a[1]), "r"(a[2]), "r"(a[3]), "r"(b[0]), "r"(b[1]));
}

// ===========================================================================
// Input projection Q/K: out = (X @ W^T + b) * scale -> bf16 hi/lo in (B,H,N,D)
// Tile 64x64, BK=16, 128 threads, each thread 8x4.
// ===========================================================================
__global__ __launch_bounds__(128) void proj_qk_kernel(
    const float* __restrict__ X, const float* __restrict__ W,
    const float* __restrict__ bias, int sel, float scale)
{
    __shared__ float As[16][65];
    __shared__ float Bs[16][65];
    __nv_bfloat16* oh = (sel == 0) ? g_qh : g_kh;
    __nv_bfloat16* ol = (sel == 0) ? g_ql : g_kl;

    const int t  = threadIdx.x;
    const int tx = t & 15, ty = t >> 4;
    const int row0 = blockIdx.x * 64, col0 = blockIdx.y * 64;
    const int lr = t >> 1;
    const int lk = (t & 1) * 8;

    float acc[8][4];
#pragma unroll
    for (int i = 0; i < 8; i++)
#pragma unroll
        for (int j = 0; j < 4; j++) acc[i][j] = 0.f;

    const float* Xr = X + (size_t)(row0 + lr) * EMB;
    const float* Wr = W + (size_t)(col0 + lr) * EMB;

    for (int k0 = 0; k0 < EMB; k0 += 16) {
        float4 a0 = *(const float4*)(Xr + k0 + lk);
        float4 a1 = *(const float4*)(Xr + k0 + lk + 4);
        float4 b0 = *(const float4*)(Wr + k0 + lk);
        float4 b1 = *(const float4*)(Wr + k0 + lk + 4);
        __syncthreads();
        As[lk+0][lr]=a0.x; As[lk+1][lr]=a0.y; As[lk+2][lr]=a0.z; As[lk+3][lr]=a0.w;
        As[lk+4][lr]=a1.x; As[lk+5][lr]=a1.y; As[lk+6][lr]=a1.z; As[lk+7][lr]=a1.w;
        Bs[lk+0][lr]=b0.x; Bs[lk+1][lr]=b0.y; Bs[lk+2][lr]=b0.z; Bs[lk+3][lr]=b0.w;
        Bs[lk+4][lr]=b1.x; Bs[lk+5][lr]=b1.y; Bs[lk+6][lr]=b1.z; Bs[lk+7][lr]=b1.w;
        __syncthreads();
#pragma unroll
        for (int kk = 0; kk < 16; kk++) {
            float a[8], b[4];
#pragma unroll
            for (int i = 0; i < 8; i++) a[i] = As[kk][ty*8+i];
#pragma unroll
            for (int j = 0; j < 4; j++) b[j] = Bs[kk][tx*4+j];
#pragma unroll
            for (int i = 0; i < 8; i++)
#pragma unroll
                for (int j = 0; j < 4; j++) acc[i][j] = fmaf(a[i], b[j], acc[i][j]);
        }
    }

    const int h  = col0 >> 6;
    const int d0 = tx * 4;
    float4 bz = *(const float4*)(bias + col0 + tx*4);
#pragma unroll
    for (int i = 0; i < 8; i++) {
        int m  = row0 + ty*8 + i;
        int bb = m >> 12, n = m & (SEQ - 1);
        float v0 = (acc[i][0] + bz.x) * scale, v1 = (acc[i][1] + bz.y) * scale;
        float v2 = (acc[i][2] + bz.z) * scale, v3 = (acc[i][3] + bz.w) * scale;
        uint32_t h01, l01, h23, l23;
        pack_hl2(v0, v1, h01, l01);
        pack_hl2(v2, v3, h23, l23);
        size_t base = ((size_t)((bb*NH + h)*SEQ + n)) * HD + d0;
        *(uint2*)&oh[base] = make_uint2(h01, h23);
        *(uint2*)&ol[base] = make_uint2(l01, l23);
    }
}

// ===========================================================================
// Input projection V: writes V^T bf16 hi/lo in (B,H,D,N)
// ===========================================================================
__global__ __launch_bounds__(128) void proj_v_kernel(
    const float* __restrict__ X, const float* __restrict__ W,
    const float* __restrict__ bias)
{
    __shared__ float As[16][65];
    __shared__ float Bs[16][65];
    __shared__ float St[64][65];

    const int t  = threadIdx.x;
    const int tx = t & 15, ty = t >> 4;
    const int row0 = blockIdx.x * 64, col0 = blockIdx.y * 64;
    const int lr = t >> 1;
    const int lk = (t & 1) * 8;

    float acc[8][4];
#pragma unroll
    for (int i = 0; i < 8; i++)
#pragma unroll
        for (int j = 0; j < 4; j++) acc[i][j] = 0.f;

    const float* Xr = X + (size_t)(row0 + lr) * EMB;
    const float* Wr = W + (size_t)(col0 + lr) * EMB;

    for (int k0 = 0; k0 < EMB; k0 += 16) {
        float4 a0 = *(const float4*)(Xr + k0 + lk);
        float4 a1 = *(const float4*)(Xr + k0 + lk + 4);
        float4 b0 = *(const float4*)(Wr + k0 + lk);
        float4 b1 = *(const float4*)(Wr + k0 + lk + 4);
        __syncthreads();
        As[lk+0][lr]=a0.x; As[lk+1][lr]=a0.y; As[lk+2][lr]=a0.z; As[lk+3][lr]=a0.w;
        As[lk+4][lr]=a1.x; As[lk+5][lr]=a1.y; As[lk+6][lr]=a1.z; As[lk+7][lr]=a1.w;
        Bs[lk+0][lr]=b0.x; Bs[lk+1][lr]=b0.y; Bs[lk+2][lr]=b0.z; Bs[lk+3][lr]=b0.w;
        Bs[lk+4][lr]=b1.x; Bs[lk+5][lr]=b1.y; Bs[lk+6][lr]=b1.z; Bs[lk+7][lr]=b1.w;
        __syncthreads();
#pragma unroll
        for (int kk = 0; kk < 16; kk++) {
            float a[8], b[4];
#pragma unroll
            for (int i = 0; i < 8; i++) a[i] = As[kk][ty*8+i];
#pragma unroll
            for (int j = 0; j < 4; j++) b[j] = Bs[kk][tx*4+j];
#pragma unroll
            for (int i = 0; i < 8; i++)
#pragma unroll
                for (int j = 0; j < 4; j++) acc[i][j] = fmaf(a[i], b[j], acc[i][j]);
        }
    }

    const int d0 = tx * 4;
    float4 bz = *(const float4*)(bias + col0 + tx*4);
    __syncthreads();
#pragma unroll
    for (int i = 0; i < 8; i++) {
        int tok = ty*8 + i;
        St[tok][d0+0] = acc[i][0] + bz.x;
        St[tok][d0+1] = acc[i][1] + bz.y;
        St[tok][d0+2] = acc[i][2] + bz.z;
        St[tok][d0+3] = acc[i][3] + bz.w;
    }
    __syncthreads();

    // transposed store: thread t -> d = t>>1, tokens (t&1)*32 .. +31
    const int h  = col0 >> 6;
    const int bb = row0 >> 12;
    const int n0 = row0 & (SEQ - 1);
    const int d  = t >> 1;
    const int j0 = (t & 1) * 32;
    uint32_t ph[16], pl[16];
#pragma unroll
    for (int jj = 0; jj < 16; jj++) {
        pack_hl2(St[j0 + 2*jj][d], St[j0 + 2*jj + 1][d], ph[jj], pl[jj]);
    }
    size_t vb = ((size_t)((bb*NH + h)*HD + d)) * SEQ + n0 + j0;
#pragma unroll
    for (int q = 0; q < 4; q++) {
        *(uint4*)&g_vth[vb + q*8] = ((uint4*)ph)[q];
        *(uint4*)&g_vtl[vb + q*8] = ((uint4*)pl)[q];
    }
}

// ===========================================================================
// Scores via mma.sync: CTA = 64 q-rows; 4 warps, warp = 16 rows x 128 keys.
// S = Qh·Kh + Qh·Kl + Ql·Kh  (scale folded into Q at projection).
// Raw scores -> attn; online per-row m/l (quad-local).
// SMEM (bf16 elems): Qh[64*72] Ql[64*72] Kh[128*72] Kl[128*72]; stride 72
// kills the 8-way bank conflicts of a 64-elem (128B) stride.
// ===========================================================================
#define SQH 0
#define SQL 4608
#define SKH 9216
#define SKL 18432
#define S_SMEM_BYTES (27648 * 2)

__global__ __launch_bounds__(128) void attn_scores_mma(float* __restrict__ attn)
{
    extern __shared__ __nv_bfloat16 sm[];
    const int t = threadIdx.x, w = t >> 5, l = t & 31;
    const int bh = blockIdx.y, q0 = blockIdx.x * 64;

    // stage Q tile (64 rows x 64 d), coalesced, padded stride 72
#pragma unroll
    for (int it = 0; it < 4; it++) {
        int j = it*128 + t, row = j >> 3, i = j & 7;
        size_t gsrc = ((size_t)(bh*SEQ + q0 + row)) * HD + i*8;
        *(uint4*)&sm[SQH + row*72 + i*8] = *(const uint4*)(g_qh + gsrc);
        *(uint4*)&sm[SQL + row*72 + i*8] = *(const uint4*)(g_ql + gsrc);
    }

    const int rA   = w*16 + (l >> 2);      // row for c0/c1 (local)
    const int gr1  = q0 + rA, gr2 = gr1 + 8;
    const size_t ar1 = ((size_t)bh*SEQ + gr1) * SEQ;
    const size_t ar2 = ((size_t)bh*SEQ + gr2) * SEQ;
    const int koffb = (l & 3) * 2;

    float m1 = -1e30f, l1 = 0.f, m2 = -1e30f, l2 = 0.f;

    for (int kt = 0; kt < SEQ/128; kt++) {
        __syncthreads();
#pragma unroll
        for (int it = 0; it < 8; it++) {
            int j = it*128 + t, row = j >> 3, i = j & 7;
            size_t gsrc = ((size_t)(bh*SEQ + kt*128 + row)) * HD + i*8;
            *(uint4*)&sm[SKH + row*72 + i*8] = *(const uint4*)(g_kh + gsrc);
            *(uint4*)&sm[SKL + row*72 + i*8] = *(const uint4*)(g_kl + gsrc);
        }
        __syncthreads();

        float acc[16][4];
#pragma unroll
        for (int nt = 0; nt < 16; nt++)
#pragma unroll
            for (int c = 0; c < 4; c++) acc[nt][c] = 0.f;

#pragma unroll
        for (int ks = 0; ks < 4; ks++) {
            const int k0 = ks*16 + koffb;
            uint32_t ah[4], al[4];
            ah[0] = *(uint32_t*)&sm[SQH + rA*72     + k0];
            ah[1] = *(uint32_t*)&sm[SQH + (rA+8)*72 + k0];
            ah[2] = *(uint32_t*)&sm[SQH + rA*72     + k0 + 8];
            ah[3] = *(uint32_t*)&sm[SQH + (rA+8)*72 + k0 + 8];
            al[0] = *(uint32_t*)&sm[SQL + rA*72     + k0];
            al[1] = *(uint32_t*)&sm[SQL + (rA+8)*72 + k0];
            al[2] = *(uint32_t*)&sm[SQL + rA*72     + k0 + 8];
            al[3] = *(uint32_t*)&sm[SQL + (rA+8)*72 + k0 + 8];
#pragma unroll
            for (int nt = 0; nt < 16; nt++) {
                const int kr = nt*8 + (l >> 2);
                uint32_t bhf[2], blf[2];
                bhf[0] = *(uint32_t*)&sm[SKH + kr*72 + k0];
                bhf[1] = *(uint32_t*)&sm[SKH + kr*72 + k0 + 8];
                blf[0] = *(uint32_t*)&sm[SKL + kr*72 + k0];
                blf[1] = *(uint32_t*)&sm[SKL + kr*72 + k0 + 8];
                mma16816(acc[nt], ah, bhf);
                mma16816(acc[nt], ah, blf);
                mma16816(acc[nt], al, bhf);
            }
        }

        // epilogue: store raw scores + online m/l
        float vmax1 = -1e30f, vmax2 = -1e30f;
#pragma unroll
        for (int nt = 0; nt < 16; nt++) {
            vmax1 = fmaxf(vmax1, fmaxf(acc[nt][0], acc[nt][1]));
            vmax2 = fmaxf(vmax2, fmaxf(acc[nt][2], acc[nt][3]));
            const int col = kt*128 + nt*8 + koffb;
            *(float2*)&attn[ar1 + col] = make_float2(acc[nt][0], acc[nt][1]);
            *(float2*)&attn[ar2 + col] = make_float2(acc[nt][2], acc[nt][3]);
        }
        vmax1 = fmaxf(vmax1, __shfl_xor_sync(0xffffffffu, vmax1, 1));
        vmax1 = fmaxf(vmax1, __shfl_xor_sync(0xffffffffu, vmax1, 2));
        vmax2 = fmaxf(vmax2, __shfl_xor_sync(0xffffffffu, vmax2, 1));
        vmax2 = fmaxf(vmax2, __shfl_xor_sync(0xffffffffu, vmax2, 2));

        const float mn1 = fmaxf(m1, vmax1), mn2 = fmaxf(m2, vmax2);
        float es1 = 0.f, es2 = 0.f;
#pragma unroll
        for (int nt = 0; nt < 16; nt++) {
            es1 += __expf(acc[nt][0] - mn1) + __expf(acc[nt][1] - mn1);
            es2 += __expf(acc[nt][2] - mn2) + __expf(acc[nt][3] - mn2);
        }
        es1 += __shfl_xor_sync(0xffffffffu, es1, 1);
        es1 += __shfl_xor_sync(0xffffffffu, es1, 2);
        es2 += __shfl_xor_sync(0xffffffffu, es2, 1);
        es2 += __shfl_xor_sync(0xffffffffu, es2, 2);

        l1 = l1 * __expf(m1 - mn1) + es1;  m1 = mn1;
        l2 = l2 * __expf(m2 - mn2) + es2;  m2 = mn2;
    }

    if ((l & 3) == 0) {
        g_m[bh*SEQ + gr1] = m1;  g_l[bh*SEQ + gr1] = l1;
        g_m[bh*SEQ + gr2] = m2;  g_l[bh*SEQ + gr2] = l2;
    }
}

// ===========================================================================
// AV via mma.sync: read raw scores in A-fragment pattern, normalize, write
// probs back (final attn), and accumulate O = P @ V with V^T staged in SMEM.
// CTA = 64 q-rows; warp = 16 rows x 64 d. SMEM: VTh[64*136] VTl[64*136].
// ===========================================================================
#define AVH 0
#define AVL 8704
#define A_SMEM_BYTES (17408 * 2)

__global__ __launch_bounds__(128) void attn_av_mma(float* __restrict__ attn)
{
    extern __shared__ __nv_bfloat16 sm[];
    const int t = threadIdx.x, w = t >> 5, l = t & 31;
    const int bh = blockIdx.y, q0 = blockIdx.x * 64;

    const int rA  = w*16 + (l >> 2);
    const int gr1 = q0 + rA, gr2 = gr1 + 8;
    const size_t ar1 = ((size_t)bh*SEQ + gr1) * SEQ;
    const size_t ar2 = ((size_t)bh*SEQ + gr2) * SEQ;
    const int koffb = (l & 3) * 2;

    const float m1  = g_m[bh*SEQ + gr1];
    const float li1 = 1.0f / g_l[bh*SEQ + gr1];
    const float m2  = g_m[bh*SEQ + gr2];
    const float li2 = 1.0f / g_l[bh*SEQ + gr2];

    float acc[8][4];
#pragma unroll
    for (int nt = 0; nt < 8; nt++)
#pragma unroll
        for (int c = 0; c < 4; c++) acc[nt][c] = 0.f;

    for (int kt = 0; kt < SEQ/128; kt++) {
        __syncthreads();
#pragma unroll
        for (int it = 0; it < 8; it++) {
            int j = it*128 + t, d = j >> 4, i = j & 15;
            size_t gsrc = ((size_t)(bh*HD + d)) * SEQ + kt*128 + i*8;
            *(uint4*)&sm[AVH + d*136 + i*8] = *(const uint4*)(g_vth + gsrc);
            *(uint4*)&sm[AVL + d*136 + i*8] = *(const uint4*)(g_vtl + gsrc);
        }
        __syncthreads();

#pragma unroll
        for (int ks = 0; ks < 8; ks++) {
            const size_t kc = (size_t)kt*128 + ks*16 + koffb;
            float2 s0 = *(float2*)&attn[ar1 + kc];
            float2 s1 = *(float2*)&attn[ar2 + kc];
            float2 s2 = *(float2*)&attn[ar1 + kc + 8];
            float2 s3 = *(float2*)&attn[ar2 + kc + 8];
            float p00 = __expf(s0.x - m1) * li1, p01 = __expf(s0.y - m1) * li1;
            float p10 = __expf(s1.x - m2) * li2, p11 = __expf(s1.y - m2) * li2;
            float p20 = __expf(s2.x - m1) * li1, p21 = __expf(s2.y - m1) * li1;
            float p30 = __expf(s3.x - m2) * li2, p31 = __expf(s3.y - m2) * li2;
            *(float2*)&attn[ar1 + kc]     = make_float2(p00, p01);
            *(float2*)&attn[ar2 + kc]     = make_float2(p10, p11);
            *(float2*)&attn[ar1 + kc + 8] = make_float2(p20, p21);
            *(float2*)&attn[ar2 + kc + 8] = make_float2(p30, p31);

            uint32_t ah[4], al[4];
            pack_hl2(p00, p01, ah[0], al[0]);
            pack_hl2(p10, p11, ah[1], al[1]);
            pack_hl2(p20, p21, ah[2], al[2]);
            pack_hl2(p30, p31, ah[3], al[3]);

            const int tk0 = ks*16 + koffb;
#pragma unroll
            for (int nt = 0; nt < 8; nt++) {
                const int dd = nt*8 + (l >> 2);
                uint32_t bhf[2], blf[2];
                bhf[0] = *(uint32_t*)&sm[AVH + dd*136 + tk0];
                bhf[1] = *(uint32_t*)&sm[AVH + dd*136 + tk0 + 8];
                blf[0] = *(uint32_t*)&sm[AVL + dd*136 + tk0];
                blf[1] = *(uint32_t*)&sm[AVL + dd*136 + tk0 + 8];
                mma16816(acc[nt], ah, bhf);
                mma16816(acc[nt], ah, blf);
                mma16816(acc[nt], al, bhf);
            }
        }
    }

#pragma unroll
    for (int nt = 0; nt < 8; nt++) {
        const int dd = nt*8 + koffb;
        *(float2*)&g_o[((size_t)bh*SEQ + gr1) * HD + dd] = make_float2(acc[nt][0], acc[nt][1]);
        *(float2*)&g_o[((size_t)bh*SEQ + gr2) * HD + dd] = make_float2(acc[nt][2], acc[nt][3]);
    }
}

// ===========================================================================
// Output projection (scalar): reads g_o in (B,H,N,D)
// ===========================================================================
__global__ __launch_bounds__(128) void proj_out_kernel(
    const float* __restrict__ W, const float* __restrict__ bias,
    float* __restrict__ out)
{
    __shared__ float As[16][65];
    __shared__ float Bs[16][65];

    const int t  = threadIdx.x;
    const int tx = t & 15, ty = t >> 4;
    const int row0 = blockIdx.x * 64, col0 = blockIdx.y * 64;
    const int lr = t >> 1;
    const int lk = (t & 1) * 8;

    const int m  = row0 + lr;
    const int bb = m >> 12, n = m & (SEQ - 1);

    float acc[8][4];
#pragma unroll
    for (int i = 0; i < 8; i++)
#pragma unroll
        for (int j = 0; j < 4; j++) acc[i][j] = 0.f;

    const float* Wr = W + (size_t)(col0 + lr) * EMB;

    for (int k0 = 0; k0 < EMB; k0 += 16) {
        int c0 = k0 + lk;
        int h = c0 >> 6, d = c0 & 63;
        const float* xr = g_o + ((size_t)((bb*NH + h)*SEQ + n)) * HD + d;
        float4 a0 = *(const float4*)(xr);
        float4 a1 = *(const float4*)(xr + 4);
        float4 b0 = *(const float4*)(Wr + k0 + lk);
        float4 b1 = *(const float4*)(Wr + k0 + lk + 4);
        __syncthreads();
        As[lk+0][lr]=a0.x; As[lk+1][lr]=a0.y; As[lk+2][lr]=a0.z; As[lk+3][lr]=a0.w;
        As[lk+4][lr]=a1.x; As[lk+5][lr]=a1.y; As[lk+6][lr]=a1.z; As[lk+7][lr]=a1.w;
        Bs[lk+0][lr]=b0.x; Bs[lk+1][lr]=b0.y; Bs[lk+2][lr]=b0.z; Bs[lk+3][lr]=b0.w;
        Bs[lk+4][lr]=b1.x; Bs[lk+5][lr]=b1.y; Bs[lk+6][lr]=b1.z; Bs[lk+7][lr]=b1.w;
        __syncthreads();
#pragma unroll
        for (int kk = 0; kk < 16; kk++) {
            float a[8], b[4];
#pragma unroll
            for (int i = 0; i < 8; i++) a[i] = As[kk][ty*8+i];
#pragma unroll
            for (int j = 0; j < 4; j++) b[j] = Bs[kk][tx*4+j];
#pragma unroll
            for (int i = 0; i < 8; i++)
#pragma unroll
                for (int j = 0; j < 4; j++) acc[i][j] = fmaf(a[i], b[j], acc[i][j]);
        }
    }

    float4 bz = *(const float4*)(bias + col0 + tx*4);
#pragma unroll
    for (int i = 0; i < 8; i++) {
        int m2 = row0 + ty*8 + i;
        float4 v;
        v.x = acc[i][0] + bz.x; v.y = acc[i][1] + bz.y;
        v.z = acc[i][2] + bz.z; v.w = acc[i][3] + bz.w;
        *(float4*)&out[(size_t)m2*EMB + col0 + tx*4] = v;
    }
}

// ---------------------------------------------------------------------------
extern "C" void kernel_launch(void* const* d_in, const int* in_sizes, int n_in,
                              void* d_out, int out_size)
{
    (void)in_sizes; (void)n_in; (void)out_size;
    const float* query = (const float*)d_in[0];
    const float* key_t = (const float*)d_in[1];
    const float* value = (const float*)d_in[2];
    const float* Wq = (const float*)d_in[3];
    const float* bq = (const float*)d_in[4];
    const float* Wk = (const float*)d_in[5];
    const float* bk = (const float*)d_in[6];
    const float* Wv = (const float*)d_in[7];
    const float* bv = (const float*)d_in[8];
    const float* Wo = (const float*)d_in[9];
    const float* bo = (const float*)d_in[10];

    float* out  = (float*)d_out;
    float* attn = out + (size_t)MTOT * EMB;

    cudaFuncSetAttribute(attn_scores_mma,
                         cudaFuncAttributeMaxDynamicSharedMemorySize, S_SMEM_BYTES);
    cudaFuncSetAttribute(attn_av_mma,
                         cudaFuncAttributeMaxDynamicSharedMemorySize, A_SMEM_BYTES);

    dim3 blk(128);
    dim3 gp(MTOT/64, EMB/64);
    proj_qk_kernel<<<gp, blk>>>(query, Wq, bq, 0, 0.125f);  // fold 1/sqrt(D)=1/8 into Q
    proj_qk_kernel<<<gp, blk>>>(key_t, Wk, bk, 1, 1.0f);
    proj_v_kernel<<<gp, blk>>>(value, Wv, bv);

    dim3 ga(SEQ/64, BHT);
    attn_scores_mma<<<ga, blk, S_SMEM_BYTES>>>(attn);
    attn_av_mma<<<ga, blk, A_SMEM_BYTES>>>(attn);

    proj_out_kernel<<<gp, blk>>>(Wo, bo, out);
}

// round 6
// speedup vs baseline: 1.9408x; 1.7369x over previous
#include <cuda_runtime.h>
#include <cuda_bf16.h>
#include <cstdint>

// MultiHeadAttention: B=2, N=4096, E=512, H=8, D=64
// Output = concat(flatten(out[B,N,E]), flatten(attn[B,H,N,N]))

#define NH   8
#define HD   64
#define SEQ  4096
#define EMB  512
#define NB   2
#define MTOT (NB * SEQ)   // 8192
#define BHT  (NB * NH)    // 16

// scratch (device globals — allocation inside kernel_launch is forbidden)
__device__ __align__(16) __nv_bfloat16 g_qh[(size_t)BHT * SEQ * HD];
__device__ __align__(16) __nv_bfloat16 g_ql[(size_t)BHT * SEQ * HD];
__device__ __align__(16) __nv_bfloat16 g_kh[(size_t)BHT * SEQ * HD];
__device__ __align__(16) __nv_bfloat16 g_kl[(size_t)BHT * SEQ * HD];
__device__ __align__(16) __nv_bfloat16 g_vth[(size_t)BHT * HD * SEQ];  // V^T: (bh,d,n)
__device__ __align__(16) __nv_bfloat16 g_vtl[(size_t)BHT * HD * SEQ];
__device__ __align__(16) __nv_bfloat16 g_oh[(size_t)MTOT * EMB];       // O: (B,N,E)
__device__ __align__(16) __nv_bfloat16 g_ol[(size_t)MTOT * EMB];
__device__ __align__(16) __nv_bfloat16 g_xh[(size_t)MTOT * EMB];       // staged X hi/lo
__device__ __align__(16) __nv_bfloat16 g_xl[(size_t)MTOT * EMB];
__device__ __align__(16) __nv_bfloat16 g_wh[(size_t)EMB * EMB];        // staged W hi/lo
__device__ __align__(16) __nv_bfloat16 g_wl[(size_t)EMB * EMB];
__device__ float g_m[BHT * SEQ];
__device__ float g_l[BHT * SEQ];

// ===========================================================================
// helpers
// ===========================================================================
__device__ __forceinline__ uint32_t pack2bf16(float lo, float hi) {
    return ((uint32_t)__bfloat16_as_ushort(__float2bfloat16(hi)) << 16) |
           (uint32_t)__bfloat16_as_ushort(__float2bfloat16(lo));
}
__device__ __forceinline__ void split_hl(float x, float& h, float& l) {
    __nv_bfloat16 b = __float2bfloat16(x);
    h = __bfloat162float(b);
    l = x - h;
}
__device__ __forceinline__ void pack_hl2(float a, float b, uint32_t& hw, uint32_t& lw) {
    float ah, al, bh, bl;
    split_hl(a, ah, al);
    split_hl(b, bh, bl);
    hw = pack2bf16(ah, bh);
    lw = pack2bf16(al, bl);
}

__device__ __forceinline__ void mma16816(float* c, const uint32_t* a, const uint32_t* b) {
    asm volatile(
        "mma.sync.aligned.m16n8k16.row.col.f32.bf16.bf16.f32 "
        "{%0,%1,%2,%3}, {%4,%5,%6,%7}, {%8,%9}, {%0,%1,%2,%3};"
        : "+f"(c[0]), "+f"(c[1]), "+f"(c[2]), "+f"(c[3])
        : "r"(a[0]), "r"(a[1]), "r"(a[2]), "r"(a[3]), "r"(b[0]), "r"(b[1]));
}

__device__ __forceinline__ uint32_t smem_u32(const void* p) {
    uint32_t a;
    asm("{ .reg .u64 t; cvta.to.shared.u64 t, %1; cvt.u32.u64 %0, t; }"
        : "=r"(a) : "l"(p));
    return a;
}
__device__ __forceinline__ void cp16(uint32_t dst, const void* src) {
    asm volatile("cp.async.cg.shared.global [%0], [%1], 16;" :: "r"(dst), "l"(src));
}
#define CP_COMMIT() asm volatile("cp.async.commit_group;")
#define CP_WAIT0()  asm volatile("cp.async.wait_group 0;")
#define CP_WAIT1()  asm volatile("cp.async.wait_group 1;")

// ===========================================================================
// fp32 -> bf16 hi/lo conversion (vectorized)
// ===========================================================================
__global__ __launch_bounds__(256) void cvt_hl_kernel(
    const float* __restrict__ src, __nv_bfloat16* __restrict__ h,
    __nv_bfloat16* __restrict__ l, int n4)
{
    int i = blockIdx.x * 256 + threadIdx.x;
    if (i < n4) {
        float4 f = ((const float4*)src)[i];
        uint32_t h01, l01, h23, l23;
        pack_hl2(f.x, f.y, h01, l01);
        pack_hl2(f.z, f.w, h23, l23);
        ((uint2*)h)[i] = make_uint2(h01, h23);
        ((uint2*)l)[i] = make_uint2(l01, l23);
    }
}

// ===========================================================================
// Tensor projection GEMM: C = A @ W^T (+bias, scale) via hi/lo bf16 mma.
// A: g_xh/g_xl (mode 0/1) or g_oh/g_ol (mode 2), row-major MxK (K=512).
// W: g_wh/g_wl row-major NxK.
// mode 0: Q -> g_qh/g_ql scatter (B,H,N,D), scale=0.125
// mode 1: K -> g_kh/g_kl scatter (B,H,N,D), scale=1
// mode 2: out -> fout fp32 (M,E)
// CTA 128 thr, tile 64x64, BK=64; warp = 16 rows x 64 cols.
// ===========================================================================
__global__ __launch_bounds__(128) void gemm_proj(
    const float* __restrict__ bias, float scale, int mode,
    float* __restrict__ fout)
{
    __shared__ __nv_bfloat16 sAh[64*72], sAl[64*72], sBh[64*72], sBl[64*72];

    const int t = threadIdx.x, w = t >> 5, l = t & 31;
    const int row0 = blockIdx.x * 64, col0 = blockIdx.y * 64;
    const int rA = w*16 + (l >> 2);
    const int koffb = (l & 3) * 2;

    const __nv_bfloat16* Ah = (mode == 2) ? g_oh : g_xh;
    const __nv_bfloat16* Al = (mode == 2) ? g_ol : g_xl;

    float acc[8][4];
#pragma unroll
    for (int nt = 0; nt < 8; nt++)
#pragma unroll
        for (int c = 0; c < 4; c++) acc[nt][c] = 0.f;

    for (int kb = 0; kb < EMB/64; kb++) {
        __syncthreads();
#pragma unroll
        for (int it = 0; it < 4; it++) {
            int j = it*128 + t, row = j >> 3, i = j & 7;
            size_t ga = (size_t)(row0 + row) * EMB + kb*64 + i*8;
            size_t gb = (size_t)(col0 + row) * EMB + kb*64 + i*8;
            *(uint4*)&sAh[row*72 + i*8] = *(const uint4*)(Ah + ga);
            *(uint4*)&sAl[row*72 + i*8] = *(const uint4*)(Al + ga);
            *(uint4*)&sBh[row*72 + i*8] = *(const uint4*)(g_wh + gb);
            *(uint4*)&sBl[row*72 + i*8] = *(const uint4*)(g_wl + gb);
        }
        __syncthreads();

#pragma unroll
        for (int ks = 0; ks < 4; ks++) {
            const int k0 = ks*16 + koffb;
            uint32_t ah[4], al[4];
            ah[0] = *(uint32_t*)&sAh[rA*72     + k0];
            ah[1] = *(uint32_t*)&sAh[(rA+8)*72 + k0];
            ah[2] = *(uint32_t*)&sAh[rA*72     + k0 + 8];
            ah[3] = *(uint32_t*)&sAh[(rA+8)*72 + k0 + 8];
            al[0] = *(uint32_t*)&sAl[rA*72     + k0];
            al[1] = *(uint32_t*)&sAl[(rA+8)*72 + k0];
            al[2] = *(uint32_t*)&sAl[rA*72     + k0 + 8];
            al[3] = *(uint32_t*)&sAl[(rA+8)*72 + k0 + 8];
#pragma unroll
            for (int nt = 0; nt < 8; nt++) {
                const int kr = nt*8 + (l >> 2);
                uint32_t bhf[2], blf[2];
                bhf[0] = *(uint32_t*)&sBh[kr*72 + k0];
                bhf[1] = *(uint32_t*)&sBh[kr*72 + k0 + 8];
                blf[0] = *(uint32_t*)&sBl[kr*72 + k0];
                blf[1] = *(uint32_t*)&sBl[kr*72 + k0 + 8];
                mma16816(acc[nt], ah, bhf);
                mma16816(acc[nt], ah, blf);
                mma16816(acc[nt], al, bhf);
            }
        }
    }

    const int gm1 = row0 + rA, gm2 = gm1 + 8;
    if (mode == 2) {
#pragma unroll
        for (int nt = 0; nt < 8; nt++) {
            const int dd = nt*8 + koffb;
            float b0 = bias[col0 + dd], b1 = bias[col0 + dd + 1];
            *(float2*)&fout[(size_t)gm1*EMB + col0 + dd] =
                make_float2(acc[nt][0] + b0, acc[nt][1] + b1);
            *(float2*)&fout[(size_t)gm2*EMB + col0 + dd] =
                make_float2(acc[nt][2] + b0, acc[nt][3] + b1);
        }
    } else {
        __nv_bfloat16* oh = (mode == 0) ? g_qh : g_kh;
        __nv_bfloat16* ol = (mode == 0) ? g_ql : g_kl;
        const int h = col0 >> 6;
        const int bb1 = gm1 >> 12, n1 = gm1 & (SEQ-1);
        const int bb2 = gm2 >> 12, n2 = gm2 & (SEQ-1);
#pragma unroll
        for (int nt = 0; nt < 8; nt++) {
            const int dd = nt*8 + koffb;
            float b0 = bias[col0 + dd], b1 = bias[col0 + dd + 1];
            uint32_t hw, lw;
            pack_hl2((acc[nt][0] + b0) * scale, (acc[nt][1] + b1) * scale, hw, lw);
            size_t base1 = ((size_t)((bb1*NH + h)*SEQ + n1)) * HD + dd;
            *(uint32_t*)&oh[base1] = hw;
            *(uint32_t*)&ol[base1] = lw;
            pack_hl2((acc[nt][2] + b0) * scale, (acc[nt][3] + b1) * scale, hw, lw);
            size_t base2 = ((size_t)((bb2*NH + h)*SEQ + n2)) * HD + dd;
            *(uint32_t*)&oh[base2] = hw;
            *(uint32_t*)&ol[base2] = lw;
        }
    }
}

// ===========================================================================
// Input projection V (scalar, with transpose epilogue): V^T hi/lo (B,H,D,N)
// ===========================================================================
__global__ __launch_bounds__(128) void proj_v_kernel(
    const float* __restrict__ X, const float* __restrict__ W,
    const float* __restrict__ bias)
{
    __shared__ float As[16][65];
    __shared__ float Bs[16][65];
    __shared__ float St[64][65];

    const int t  = threadIdx.x;
    const int tx = t & 15, ty = t >> 4;
    const int row0 = blockIdx.x * 64, col0 = blockIdx.y * 64;
    const int lr = t >> 1;
    const int lk = (t & 1) * 8;

    float acc[8][4];
#pragma unroll
    for (int i = 0; i < 8; i++)
#pragma unroll
        for (int j = 0; j < 4; j++) acc[i][j] = 0.f;

    const float* Xr = X + (size_t)(row0 + lr) * EMB;
    const float* Wr = W + (size_t)(col0 + lr) * EMB;

    for (int k0 = 0; k0 < EMB; k0 += 16) {
        float4 a0 = *(const float4*)(Xr + k0 + lk);
        float4 a1 = *(const float4*)(Xr + k0 + lk + 4);
        float4 b0 = *(const float4*)(Wr + k0 + lk);
        float4 b1 = *(const float4*)(Wr + k0 + lk + 4);
        __syncthreads();
        As[lk+0][lr]=a0.x; As[lk+1][lr]=a0.y; As[lk+2][lr]=a0.z; As[lk+3][lr]=a0.w;
        As[lk+4][lr]=a1.x; As[lk+5][lr]=a1.y; As[lk+6][lr]=a1.z; As[lk+7][lr]=a1.w;
        Bs[lk+0][lr]=b0.x; Bs[lk+1][lr]=b0.y; Bs[lk+2][lr]=b0.z; Bs[lk+3][lr]=b0.w;
        Bs[lk+4][lr]=b1.x; Bs[lk+5][lr]=b1.y; Bs[lk+6][lr]=b1.z; Bs[lk+7][lr]=b1.w;
        __syncthreads();
#pragma unroll
        for (int kk = 0; kk < 16; kk++) {
            float a[8], b[4];
#pragma unroll
            for (int i = 0; i < 8; i++) a[i] = As[kk][ty*8+i];
#pragma unroll
            for (int j = 0; j < 4; j++) b[j] = Bs[kk][tx*4+j];
#pragma unroll
            for (int i = 0; i < 8; i++)
#pragma unroll
                for (int j = 0; j < 4; j++) acc[i][j] = fmaf(a[i], b[j], acc[i][j]);
        }
    }

    const int d0 = tx * 4;
    float4 bz = *(const float4*)(bias + col0 + tx*4);
    __syncthreads();
#pragma unroll
    for (int i = 0; i < 8; i++) {
        int tok = ty*8 + i;
        St[tok][d0+0] = acc[i][0] + bz.x;
        St[tok][d0+1] = acc[i][1] + bz.y;
        St[tok][d0+2] = acc[i][2] + bz.z;
        St[tok][d0+3] = acc[i][3] + bz.w;
    }
    __syncthreads();

    const int h  = col0 >> 6;
    const int bb = row0 >> 12;
    const int n0 = row0 & (SEQ - 1);
    const int d  = t >> 1;
    const int j0 = (t & 1) * 32;
    uint32_t ph[16], pl[16];
#pragma unroll
    for (int jj = 0; jj < 16; jj++) {
        pack_hl2(St[j0 + 2*jj][d], St[j0 + 2*jj + 1][d], ph[jj], pl[jj]);
    }
    size_t vb = ((size_t)((bb*NH + h)*HD + d)) * SEQ + n0 + j0;
#pragma unroll
    for (int q = 0; q < 4; q++) {
        *(uint4*)&g_vth[vb + q*8] = ((uint4*)ph)[q];
        *(uint4*)&g_vtl[vb + q*8] = ((uint4*)pl)[q];
    }
}

// ===========================================================================
// Scores via mma.sync + cp.async double-buffered K tiles (KT=64).
// CTA = 64 q-rows; 4 warps, warp = 16 rows x 64 keys per iter.
// SMEM elems: Qh[4608] Ql[4608] Kh0 Kh1 Kl0 Kl1 [4608 each] = 55296B dyn.
// ===========================================================================
#define SOQH 0
#define SOQL 4608
#define SOKH 9216
#define SOKL 18432
#define S_SMEM_BYTES (27648 * 2)

__global__ __launch_bounds__(128) void attn_scores_mma(float* __restrict__ attn)
{
    extern __shared__ __nv_bfloat16 sm[];
    const uint32_t sb = smem_u32(sm);
    const int t = threadIdx.x, w = t >> 5, l = t & 31;
    const int bh = blockIdx.y, q0 = blockIdx.x * 64;

    // Q tile (64 x 64), padded stride 72
#pragma unroll
    for (int it = 0; it < 4; it++) {
        int j = it*128 + t, row = j >> 3, i = j & 7;
        size_t gsrc = ((size_t)(bh*SEQ + q0 + row)) * HD + i*8;
        *(uint4*)&sm[SOQH + row*72 + i*8] = *(const uint4*)(g_qh + gsrc);
        *(uint4*)&sm[SOQL + row*72 + i*8] = *(const uint4*)(g_ql + gsrc);
    }

    const int rA   = w*16 + (l >> 2);
    const int gr1  = q0 + rA, gr2 = gr1 + 8;
    const size_t ar1 = ((size_t)bh*SEQ + gr1) * SEQ;
    const size_t ar2 = ((size_t)bh*SEQ + gr2) * SEQ;
    const int koffb = (l & 3) * 2;

    float m1 = -1e30f, l1 = 0.f, m2 = -1e30f, l2 = 0.f;

    // prefetch K tile 0 into stage 0
    {
#pragma unroll
        for (int it = 0; it < 4; it++) {
            int j = it*128 + t, row = j >> 3, i = j & 7;
            size_t gsrc = ((size_t)(bh*SEQ + row)) * HD + i*8;
            cp16(sb + (SOKH + row*72 + i*8)*2, g_kh + gsrc);
            cp16(sb + (SOKL + row*72 + i*8)*2, g_kl + gsrc);
        }
        CP_COMMIT();
    }

    for (int kt = 0; kt < SEQ/64; kt++) {
        const int cur = kt & 1;
        if (kt + 1 < SEQ/64) {
            const int nxt = cur ^ 1;
#pragma unroll
            for (int it = 0; it < 4; it++) {
                int j = it*128 + t, row = j >> 3, i = j & 7;
                size_t gsrc = ((size_t)(bh*SEQ + (kt+1)*64 + row)) * HD + i*8;
                cp16(sb + (SOKH + nxt*4608 + row*72 + i*8)*2, g_kh + gsrc);
                cp16(sb + (SOKL + nxt*4608 + row*72 + i*8)*2, g_kl + gsrc);
            }
            CP_COMMIT();
            CP_WAIT1();
        } else {
            CP_WAIT0();
        }
        __syncthreads();

        float acc[8][4];
#pragma unroll
        for (int nt = 0; nt < 8; nt++)
#pragma unroll
            for (int c = 0; c < 4; c++) acc[nt][c] = 0.f;

        const int kbase = SOKH + cur*4608;
        const int lbase = SOKL + cur*4608;
#pragma unroll
        for (int ks = 0; ks < 4; ks++) {
            const int k0 = ks*16 + koffb;
            uint32_t ah[4], al[4];
            ah[0] = *(uint32_t*)&sm[SOQH + rA*72     + k0];
            ah[1] = *(uint32_t*)&sm[SOQH + (rA+8)*72 + k0];
            ah[2] = *(uint32_t*)&sm[SOQH + rA*72     + k0 + 8];
            ah[3] = *(uint32_t*)&sm[SOQH + (rA+8)*72 + k0 + 8];
            al[0] = *(uint32_t*)&sm[SOQL + rA*72     + k0];
            al[1] = *(uint32_t*)&sm[SOQL + (rA+8)*72 + k0];
            al[2] = *(uint32_t*)&sm[SOQL + rA*72     + k0 + 8];
            al[3] = *(uint32_t*)&sm[SOQL + (rA+8)*72 + k0 + 8];
#pragma unroll
            for (int nt = 0; nt < 8; nt++) {
                const int kr = nt*8 + (l >> 2);
                uint32_t bhf[2], blf[2];
                bhf[0] = *(uint32_t*)&sm[kbase + kr*72 + k0];
                bhf[1] = *(uint32_t*)&sm[kbase + kr*72 + k0 + 8];
                blf[0] = *(uint32_t*)&sm[lbase + kr*72 + k0];
                blf[1] = *(uint32_t*)&sm[lbase + kr*72 + k0 + 8];
                mma16816(acc[nt], ah, bhf);
                mma16816(acc[nt], ah, blf);
                mma16816(acc[nt], al, bhf);
            }
        }

        // epilogue: store raw scores + online m/l
        float vmax1 = -1e30f, vmax2 = -1e30f;
#pragma unroll
        for (int nt = 0; nt < 8; nt++) {
            vmax1 = fmaxf(vmax1, fmaxf(acc[nt][0], acc[nt][1]));
            vmax2 = fmaxf(vmax2, fmaxf(acc[nt][2], acc[nt][3]));
            const int col = kt*64 + nt*8 + koffb;
            *(float2*)&attn[ar1 + col] = make_float2(acc[nt][0], acc[nt][1]);
            *(float2*)&attn[ar2 + col] = make_float2(acc[nt][2], acc[nt][3]);
        }
        vmax1 = fmaxf(vmax1, __shfl_xor_sync(0xffffffffu, vmax1, 1));
        vmax1 = fmaxf(vmax1, __shfl_xor_sync(0xffffffffu, vmax1, 2));
        vmax2 = fmaxf(vmax2, __shfl_xor_sync(0xffffffffu, vmax2, 1));
        vmax2 = fmaxf(vmax2, __shfl_xor_sync(0xffffffffu, vmax2, 2));

        const float mn1 = fmaxf(m1, vmax1), mn2 = fmaxf(m2, vmax2);
        float es1 = 0.f, es2 = 0.f;
#pragma unroll
        for (int nt = 0; nt < 8; nt++) {
            es1 += __expf(acc[nt][0] - mn1) + __expf(acc[nt][1] - mn1);
            es2 += __expf(acc[nt][2] - mn2) + __expf(acc[nt][3] - mn2);
        }
        es1 += __shfl_xor_sync(0xffffffffu, es1, 1);
        es1 += __shfl_xor_sync(0xffffffffu, es1, 2);
        es2 += __shfl_xor_sync(0xffffffffu, es2, 1);
        es2 += __shfl_xor_sync(0xffffffffu, es2, 2);

        l1 = l1 * __expf(m1 - mn1) + es1;  m1 = mn1;
        l2 = l2 * __expf(m2 - mn2) + es2;  m2 = mn2;

        __syncthreads();
    }

    if ((l & 3) == 0) {
        g_m[bh*SEQ + gr1] = m1;  g_l[bh*SEQ + gr1] = l1;
        g_m[bh*SEQ + gr2] = m2;  g_l[bh*SEQ + gr2] = l2;
    }
}

// ===========================================================================
// AV via mma.sync + cp.async double-buffered V tiles (KT=64): read raw
// scores, normalize, write probs back (final attn), accumulate O = P @ V,
// epilogue stores O as bf16 hi/lo in (B,N,E) for the tensor out-projection.
// SMEM: Vh0 Vh1 Vl0 Vl1 [4608 each] = 36864B static.
// ===========================================================================
__global__ __launch_bounds__(128) void attn_av_mma(float* __restrict__ attn)
{
    __shared__ __nv_bfloat16 sm[18432];
    const uint32_t sb = smem_u32(sm);
    const int t = threadIdx.x, w = t >> 5, l = t & 31;
    const int bh = blockIdx.y, q0 = blockIdx.x * 64;

    const int rA  = w*16 + (l >> 2);
    const int gr1 = q0 + rA, gr2 = gr1 + 8;
    const size_t ar1 = ((size_t)bh*SEQ + gr1) * SEQ;
    const size_t ar2 = ((size_t)bh*SEQ + gr2) * SEQ;
    const int koffb = (l & 3) * 2;

    const float m1  = g_m[bh*SEQ + gr1];
    const float li1 = 1.0f / g_l[bh*SEQ + gr1];
    const float m2  = g_m[bh*SEQ + gr2];
    const float li2 = 1.0f / g_l[bh*SEQ + gr2];

    float acc[8][4];
#pragma unroll
    for (int nt = 0; nt < 8; nt++)
#pragma unroll
        for (int c = 0; c < 4; c++) acc[nt][c] = 0.f;

    // V stage layout: Vh at stage*4608, Vl at 9216 + stage*4608
    {
#pragma unroll
        for (int it = 0; it < 4; it++) {
            int j = it*128 + t, d = j >> 3, i = j & 7;
            size_t gsrc = ((size_t)(bh*HD + d)) * SEQ + i*8;
            cp16(sb + (d*72 + i*8)*2, g_vth + gsrc);
            cp16(sb + (9216 + d*72 + i*8)*2, g_vtl + gsrc);
        }
        CP_COMMIT();
    }

    for (int kt = 0; kt < SEQ/64; kt++) {
        const int cur = kt & 1;
        if (kt + 1 < SEQ/64) {
            const int nxt = cur ^ 1;
#pragma unroll
            for (int it = 0; it < 4; it++) {
                int j = it*128 + t, d = j >> 3, i = j & 7;
                size_t gsrc = ((size_t)(bh*HD + d)) * SEQ + (kt+1)*64 + i*8;
                cp16(sb + (nxt*4608 + d*72 + i*8)*2, g_vth + gsrc);
                cp16(sb + (9216 + nxt*4608 + d*72 + i*8)*2, g_vtl + gsrc);
            }
            CP_COMMIT();
            CP_WAIT1();
        } else {
            CP_WAIT0();
        }
        __syncthreads();

        const int vh = cur*4608;
        const int vl = 9216 + cur*4608;
#pragma unroll
        for (int ks = 0; ks < 4; ks++) {
            const size_t kc = (size_t)kt*64 + ks*16 + koffb;
            float2 s0 = *(float2*)&attn[ar1 + kc];
            float2 s1 = *(float2*)&attn[ar2 + kc];
            float2 s2 = *(float2*)&attn[ar1 + kc + 8];
            float2 s3 = *(float2*)&attn[ar2 + kc + 8];
            float p00 = __expf(s0.x - m1) * li1, p01 = __expf(s0.y - m1) * li1;
            float p10 = __expf(s1.x - m2) * li2, p11 = __expf(s1.y - m2) * li2;
            float p20 = __expf(s2.x - m1) * li1, p21 = __expf(s2.y - m1) * li1;
            float p30 = __expf(s3.x - m2) * li2, p31 = __expf(s3.y - m2) * li2;
            *(float2*)&attn[ar1 + kc]     = make_float2(p00, p01);
            *(float2*)&attn[ar2 + kc]     = make_float2(p10, p11);
            *(float2*)&attn[ar1 + kc + 8] = make_float2(p20, p21);
            *(float2*)&attn[ar2 + kc + 8] = make_float2(p30, p31);

            uint32_t ah[4], al[4];
            pack_hl2(p00, p01, ah[0], al[0]);
            pack_hl2(p10, p11, ah[1], al[1]);
            pack_hl2(p20, p21, ah[2], al[2]);
            pack_hl2(p30, p31, ah[3], al[3]);

            const int tk0 = ks*16 + koffb;
#pragma unroll
            for (int nt = 0; nt < 8; nt++) {
                const int dd = nt*8 + (l >> 2);
                uint32_t bhf[2], blf[2];
                bhf[0] = *(uint32_t*)&sm[vh + dd*72 + tk0];
                bhf[1] = *(uint32_t*)&sm[vh + dd*72 + tk0 + 8];
                blf[0] = *(uint32_t*)&sm[vl + dd*72 + tk0];
                blf[1] = *(uint32_t*)&sm[vl + dd*72 + tk0 + 8];
                mma16816(acc[nt], ah, bhf);
                mma16816(acc[nt], ah, blf);
                mma16816(acc[nt], al, bhf);
            }
        }
        __syncthreads();
    }

    // store O as bf16 hi/lo in (B,N,E)
    const int bb = bh >> 3, hh = bh & 7;
#pragma unroll
    for (int nt = 0; nt < 8; nt++) {
        const int dd = nt*8 + koffb;
        uint32_t hw, lw;
        pack_hl2(acc[nt][0], acc[nt][1], hw, lw);
        size_t b1 = ((size_t)(bb*SEQ + gr1)) * EMB + hh*64 + dd;
        *(uint32_t*)&g_oh[b1] = hw;
        *(uint32_t*)&g_ol[b1] = lw;
        pack_hl2(acc[nt][2], acc[nt][3], hw, lw);
        size_t b2 = ((size_t)(bb*SEQ + gr2)) * EMB + hh*64 + dd;
        *(uint32_t*)&g_oh[b2] = hw;
        *(uint32_t*)&g_ol[b2] = lw;
    }
}

// ---------------------------------------------------------------------------
extern "C" void kernel_launch(void* const* d_in, const int* in_sizes, int n_in,
                              void* d_out, int out_size)
{
    (void)in_sizes; (void)n_in; (void)out_size;
    const float* query = (const float*)d_in[0];
    const float* key_t = (const float*)d_in[1];
    const float* value = (const float*)d_in[2];
    const float* Wq = (const float*)d_in[3];
    const float* bq = (const float*)d_in[4];
    const float* Wk = (const float*)d_in[5];
    const float* bk = (const float*)d_in[6];
    const float* Wv = (const float*)d_in[7];
    const float* bv = (const float*)d_in[8];
    const float* Wo = (const float*)d_in[9];
    const float* bo = (const float*)d_in[10];

    float* out  = (float*)d_out;
    float* attn = out + (size_t)MTOT * EMB;

    cudaFuncSetAttribute(attn_scores_mma,
                         cudaFuncAttributeMaxDynamicSharedMemorySize, S_SMEM_BYTES);

    // get symbol addresses for cvt destinations (host-side queries, capture-safe)
    __nv_bfloat16 *xh, *xl, *wh, *wl;
    cudaGetSymbolAddress((void**)&xh, g_xh);
    cudaGetSymbolAddress((void**)&xl, g_xl);
    cudaGetSymbolAddress((void**)&wh, g_wh);
    cudaGetSymbolAddress((void**)&wl, g_wl);

    dim3 blk(128);
    dim3 gg(MTOT/64, EMB/64);

    const int nx4 = MTOT*EMB/4, nw4 = EMB*EMB/4;

    // Q projection
    cvt_hl_kernel<<<(nx4+255)/256, 256>>>(query, xh, xl, nx4);
    cvt_hl_kernel<<<(nw4+255)/256, 256>>>(Wq, wh, wl, nw4);
    gemm_proj<<<gg, blk>>>(bq, 0.125f, 0, nullptr);   // fold 1/sqrt(D) into Q

    // K projection
    cvt_hl_kernel<<<(nx4+255)/256, 256>>>(key_t, xh, xl, nx4);
    cvt_hl_kernel<<<(nw4+255)/256, 256>>>(Wk, wh, wl, nw4);
    gemm_proj<<<gg, blk>>>(bk, 1.0f, 1, nullptr);

    // V projection (scalar, transpose epilogue)
    proj_v_kernel<<<gg, blk>>>(value, Wv, bv);

    // attention
    dim3 ga(SEQ/64, BHT);
    attn_scores_mma<<<ga, blk, S_SMEM_BYTES>>>(attn);
    attn_av_mma<<<ga, blk>>>(attn);

    // output projection
    cvt_hl_kernel<<<(nw4+255)/256, 256>>>(Wo, wh, wl, nw4);
    gemm_proj<<<gg, blk>>>(bo, 1.0f, 2, out);
}